// round 11
// baseline (speedup 1.0000x reference)
#include <cuda_runtime.h>
#include <cuda_fp16.h>
#include <cstdint>

// ---------------------------------------------------------------------------
// MoE grouped GEMM: fp16 mma.sync (f32 accum), A gathered as fp32 directly
// from inp via cp.async and converted to fp16 in registers (no cvt_inp pass).
// B pre-converted to fp16 on a forked stream. 3-stage cp.async pipeline.
// out[i] = weight[gate[i]] @ inp[i]
//   inp: [65536,512] f32, gate: [65536] i32, weight: [64,512,512] f32
// ---------------------------------------------------------------------------

#define N_TOKENS 65536
#define D_IN     512
#define D_OUT    512
#define N_EXP    64

#define TM 128
#define TN 128
#define BK 32                   // k-chunk (fp32 A row = 128B)
#define NITER (D_IN / BK)       // 16
#define NSTAGE 3
#define MAX_TILES 1024

#define STRIDE_A 36             // floats per A smem row (144B, conflict-free)
#define STRIDE_BH 40            // halves per B smem row (80B)

#define TILEA_B  (TM * STRIDE_A * 4)         // 18432
#define TILEB_B  (TM * STRIDE_BH * 2)        // 10240
#define STAGE_B  (TILEA_B + TILEB_B)         // 28672
#define SM_A     1024
#define SMEM_TOTAL (SM_A + NSTAGE * STAGE_B) // 87040 -> 2 CTAs/SM

__device__ int g_counts[N_EXP];
__device__ int g_cursor[N_EXP];
__device__ int g_offsets[N_EXP];
__device__ int g_perm[N_TOKENS];
__device__ int g_tile_expert[MAX_TILES];
__device__ int g_tile_start[MAX_TILES];
__device__ int g_tile_rows[MAX_TILES];
__device__ int g_ntiles;

__device__ __align__(16) __half w_h[N_EXP * D_OUT * D_IN];

// ---------------- prep kernels ----------------
__global__ void k_zero() {
    int t = threadIdx.x;
    if (t < N_EXP) { g_counts[t] = 0; g_cursor[t] = 0; }
}

__global__ void k_hist(const int4* __restrict__ gate4) {
    __shared__ int h[N_EXP];
    int t = threadIdx.x;
    if (t < N_EXP) h[t] = 0;
    __syncthreads();
    int4 g = gate4[blockIdx.x * blockDim.x + t];
    atomicAdd(&h[g.x], 1); atomicAdd(&h[g.y], 1);
    atomicAdd(&h[g.z], 1); atomicAdd(&h[g.w], 1);
    __syncthreads();
    if (t < N_EXP && h[t]) atomicAdd(&g_counts[t], h[t]);
}

__global__ void k_build() {
    __shared__ int ws[2], wt[2];
    int e = threadIdx.x;
    int c = g_counts[e];
    int x = c;
    #pragma unroll
    for (int d = 1; d < 32; d <<= 1) {
        int v = __shfl_up_sync(0xFFFFFFFFu, x, d);
        if ((e & 31) >= d) x += v;
    }
    if ((e & 31) == 31) ws[e >> 5] = x;
    __syncthreads();
    int off = x - c + ((e >= 32) ? ws[0] : 0);
    g_offsets[e] = off;

    int nt = (c + TM - 1) / TM;
    int y = nt;
    #pragma unroll
    for (int d = 1; d < 32; d <<= 1) {
        int v = __shfl_up_sync(0xFFFFFFFFu, y, d);
        if ((e & 31) >= d) y += v;
    }
    if ((e & 31) == 31) wt[e >> 5] = y;
    __syncthreads();
    int tbase = y - nt + ((e >= 32) ? wt[0] : 0);
    for (int s = 0, i = 0; s < c; s += TM, i++) {
        g_tile_expert[tbase + i] = e;
        g_tile_start[tbase + i]  = off + s;
        g_tile_rows[tbase + i]   = min(TM, c - s);
    }
    if (e == 63) g_ntiles = tbase + nt;
}

__global__ void k_scatter(const int* __restrict__ gate) {
    __shared__ int lh[N_EXP], lb[N_EXP];
    int t = threadIdx.x;
    if (t < N_EXP) lh[t] = 0;
    __syncthreads();
    int base = blockIdx.x * 1024;
    int4 g = ((const int4*)(gate + base))[t];
    int r0 = atomicAdd(&lh[g.x], 1);
    int r1 = atomicAdd(&lh[g.y], 1);
    int r2 = atomicAdd(&lh[g.z], 1);
    int r3 = atomicAdd(&lh[g.w], 1);
    __syncthreads();
    if (t < N_EXP) {
        int c = lh[t];
        lb[t] = c ? (g_offsets[t] + atomicAdd(&g_cursor[t], c)) : 0;
    }
    __syncthreads();
    int tok = base + t * 4;
    g_perm[lb[g.x] + r0] = tok + 0;
    g_perm[lb[g.y] + r1] = tok + 1;
    g_perm[lb[g.z] + r2] = tok + 2;
    g_perm[lb[g.w] + r3] = tok + 3;
}

__global__ void k_cvt_w(const float4* __restrict__ w4) {
    int idx = blockIdx.x * blockDim.x + threadIdx.x;
    float4 v = w4[idx];
    __half2* dst = (__half2*)(w_h + (size_t)idx * 4);
    dst[0] = __floats2half2_rn(v.x, v.y);
    dst[1] = __floats2half2_rn(v.z, v.w);
}

// ---------------- GEMM helpers ----------------
__device__ __forceinline__ uint32_t smem_u32(const void* p) {
    uint32_t a;
    asm("{ .reg .u64 t; cvta.to.shared.u64 t, %1; cvt.u32.u64 %0, t; }" : "=r"(a) : "l"(p));
    return a;
}
__device__ __forceinline__ void cp16(uint32_t dst, const void* src) {
    asm volatile("cp.async.cg.shared.global [%0], [%1], 16;"
                 :: "r"(dst), "l"(src) : "memory");
}
__device__ __forceinline__ void cp16z(uint32_t dst, const void* src, uint32_t srcsize) {
    asm volatile("cp.async.cg.shared.global [%0], [%1], 16, %2;"
                 :: "r"(dst), "l"(src), "r"(srcsize) : "memory");
}
__device__ __forceinline__ void ldm_x4(uint32_t* r, uint32_t a) {
    asm volatile("ldmatrix.sync.aligned.m8n8.x4.shared.b16 {%0,%1,%2,%3}, [%4];"
                 : "=r"(r[0]), "=r"(r[1]), "=r"(r[2]), "=r"(r[3]) : "r"(a));
}
// Pack two fp32 into fp16x2 (RN): result.lo = lo, result.hi = hi.
__device__ __forceinline__ uint32_t f2h2(float lo, float hi) {
    uint32_t r;
    asm("cvt.rn.f16x2.f32 %0, %1, %2;" : "=r"(r) : "f"(hi), "f"(lo));
    return r;
}
__device__ __forceinline__ void mma_f16(float* d, const uint32_t* a, const uint32_t* b) {
    asm volatile(
        "mma.sync.aligned.m16n8k16.row.col.f32.f16.f16.f32 "
        "{%0,%1,%2,%3}, {%4,%5,%6,%7}, {%8,%9}, {%0,%1,%2,%3};"
        : "+f"(d[0]), "+f"(d[1]), "+f"(d[2]), "+f"(d[3])
        : "r"(a[0]), "r"(a[1]), "r"(a[2]), "r"(a[3]), "r"(b[0]), "r"(b[1]));
}

// ---------------- tensor-core GEMM (fused A conversion) ----------------
__global__ __launch_bounds__(256, 2) void k_gemm(const float* __restrict__ inp,
                                                 float* __restrict__ out) {
    int tile = blockIdx.x;
    if (tile >= g_ntiles) return;
    int e     = g_tile_expert[tile];
    int start = g_tile_start[tile];
    int nrows = g_tile_rows[tile];
    int otile = blockIdx.y * TN;

    extern __shared__ char smem[];
    uint32_t sb = smem_u32(smem);
    int* rows_s = (int*)smem;

    int tid = threadIdx.x;
    int wid = tid >> 5, lid = tid & 31;
    int wm = wid & 1, wn = wid >> 1;     // warp tile: rows wm*64, cols wn*32
    int g  = lid >> 2, c = lid & 3;

    if (tid < TM) rows_s[tid] = (tid < nrows) ? g_perm[start + tid] : -1;
    __syncthreads();

    // A cp.async: rows arow_q + l*32 (l=0..3), 16B segment aseg (128B row)
    int arow_q = tid >> 3, aseg = tid & 7;
    const float* asrc[4]; uint32_t asz[4];
    #pragma unroll
    for (int l = 0; l < 4; l++) {
        int tok = rows_s[arow_q + l * 32];
        asz[l]  = (tok >= 0) ? 16u : 0u;
        asrc[l] = inp + (size_t)((tok < 0) ? 0 : tok) * D_IN + aseg * 4;
    }
    uint32_t adst0 = sb + SM_A + arow_q * (STRIDE_A * 4) + aseg * 16;

    // B cp.async: rows brow + l*64 (l=0..1), 16B segment bseg (64B row)
    int brow = tid >> 2, bseg = tid & 3;
    const __half* bsrc = w_h + (size_t)(e * D_OUT + otile + brow) * D_IN + bseg * 8;
    uint32_t bdst0 = sb + SM_A + TILEA_B + brow * (STRIDE_BH * 2) + bseg * 16;

    // B ldmatrix lane address (within stage's B tile)
    uint32_t b_lm = (uint32_t)((wn * 32 + ((lid >> 4) & 1) * 8 + (lid & 7)) * (STRIDE_BH * 2)
                               + ((lid >> 3) & 1) * 16);

    float acc[4][4][4];
    #pragma unroll
    for (int mi = 0; mi < 4; mi++)
        #pragma unroll
        for (int ni = 0; ni < 4; ni++)
            #pragma unroll
            for (int q = 0; q < 4; q++) acc[mi][ni][q] = 0.f;

    // Prologue: stages 0 and 1
    #pragma unroll
    for (int st = 0; st < 2; st++) {
        uint32_t so = st * STAGE_B;
        int kk = st * BK;
        #pragma unroll
        for (int l = 0; l < 4; l++)
            cp16z(adst0 + so + l * (32 * STRIDE_A * 4), asrc[l] + kk, asz[l]);
        #pragma unroll
        for (int l = 0; l < 2; l++)
            cp16(bdst0 + so + l * (64 * STRIDE_BH * 2), bsrc + kk + (size_t)l * 64 * D_IN);
        asm volatile("cp.async.commit_group;" ::: "memory");
    }

    for (int it = 0; it < NITER; it++) {
        if (it == NITER - 1)
            asm volatile("cp.async.wait_group 0;" ::: "memory");
        else
            asm volatile("cp.async.wait_group 1;" ::: "memory");
        __syncthreads();

        if (it + 2 < NITER) {
            uint32_t so = ((it + 2) % NSTAGE) * STAGE_B;
            int kk = (it + 2) * BK;
            #pragma unroll
            for (int l = 0; l < 4; l++)
                cp16z(adst0 + so + l * (32 * STRIDE_A * 4), asrc[l] + kk, asz[l]);
            #pragma unroll
            for (int l = 0; l < 2; l++)
                cp16(bdst0 + so + l * (64 * STRIDE_BH * 2), bsrc + kk + (size_t)l * 64 * D_IN);
            asm volatile("cp.async.commit_group;" ::: "memory");
        }

        uint32_t so = (it % NSTAGE) * STAGE_B;
        const float2* Af = (const float2*)(smem + SM_A + so);
        uint32_t bL = sb + SM_A + so + TILEA_B + b_lm;
        #pragma unroll
        for (int ks = 0; ks < 2; ks++) {          // 2 k-steps of k16
            // A fragments: LDS.64 fp32 pairs + packed cvt to f16x2 (RN)
            uint32_t af[4][4];
            #pragma unroll
            for (int mi = 0; mi < 4; mi++) {
                int rbase = (wm * 64 + mi * 16 + g) * (STRIDE_A / 2) + ks * 8 + c;
                float2 p00 = Af[rbase];                      // row g,   k 2c..2c+1
                float2 p10 = Af[rbase + 8 * (STRIDE_A / 2)]; // row g+8, k 2c..2c+1
                float2 p01 = Af[rbase + 4];                  // row g,   k +8
                float2 p11 = Af[rbase + 8 * (STRIDE_A / 2) + 4];
                af[mi][0] = f2h2(p00.x, p00.y);
                af[mi][1] = f2h2(p10.x, p10.y);
                af[mi][2] = f2h2(p01.x, p01.y);
                af[mi][3] = f2h2(p11.x, p11.y);
            }
            // B fragments: 2 ldmatrix.x4, each covering 2 n8 tiles x k16
            uint32_t bf[2][4];
            #pragma unroll
            for (int p = 0; p < 2; p++)
                ldm_x4(bf[p], bL + p * (16 * STRIDE_BH * 2) + ks * 32);
            #pragma unroll
            for (int mi = 0; mi < 4; mi++)
                #pragma unroll
                for (int ni = 0; ni < 4; ni++)
                    mma_f16(acc[mi][ni], af[mi], &bf[ni >> 1][(ni & 1) * 2]);
        }
    }

    // Epilogue: thread (g,c) owns rows g/g+8, cols 2c/2c+1 of each m16n8 tile
    #pragma unroll
    for (int mi = 0; mi < 4; mi++) {
        int r0 = wm * 64 + mi * 16 + g;
        int row0e = rows_s[r0];
        int row1e = rows_s[r0 + 8];
        #pragma unroll
        for (int ni = 0; ni < 4; ni++) {
            int col = otile + wn * 32 + ni * 8 + 2 * c;
            if (row0e >= 0)
                *(float2*)(out + (size_t)row0e * D_OUT + col) =
                    make_float2(acc[mi][ni][0], acc[mi][ni][1]);
            if (row1e >= 0)
                *(float2*)(out + (size_t)row1e * D_OUT + col) =
                    make_float2(acc[mi][ni][2], acc[mi][ni][3]);
        }
    }
}

extern "C" void kernel_launch(void* const* d_in, const int* in_sizes, int n_in,
                              void* d_out, int out_size) {
    const float* inp    = (const float*)d_in[0];
    const int*   gate   = (const int*)d_in[1];
    const float* weight = (const float*)d_in[2];
    float*       out    = (float*)d_out;

    static cudaStream_t s2 = nullptr;
    static cudaEvent_t ev_fork = nullptr, ev_w = nullptr;
    if (!s2) {
        cudaStreamCreateWithFlags(&s2, cudaStreamNonBlocking);
        cudaEventCreateWithFlags(&ev_fork, cudaEventDisableTiming);
        cudaEventCreateWithFlags(&ev_w, cudaEventDisableTiming);
    }

    cudaFuncSetAttribute(k_gemm, cudaFuncAttributeMaxDynamicSharedMemorySize, SMEM_TOTAL);

    // Fork: weight conversion on s2, concurrent with token prep chain.
    cudaEventRecord(ev_fork, 0);
    cudaStreamWaitEvent(s2, ev_fork, 0);
    k_cvt_w<<<(N_EXP * D_OUT * D_IN / 4) / 256, 256, 0, s2>>>((const float4*)weight);
    cudaEventRecord(ev_w, s2);

    // Token prep on stream 0.
    k_zero<<<1, 64>>>();
    k_hist<<<N_TOKENS / (256 * 4), 256>>>((const int4*)gate);
    k_build<<<1, 64>>>();
    k_scatter<<<N_TOKENS / 1024, 256>>>(gate);

    // Join w_h before GEMM.
    cudaStreamWaitEvent(0, ev_w, 0);
    dim3 grid(640, D_OUT / TN);
    k_gemm<<<grid, 256, SMEM_TOTAL>>>(inp, out);
}

// round 12
// speedup vs baseline: 1.3018x; 1.3018x over previous
#include <cuda_runtime.h>
#include <cuda_fp16.h>
#include <cstdint>

// ---------------------------------------------------------------------------
// MoE grouped GEMM: fp16 mma.sync (f32 accum) + cp.async 3-stage pipeline +
// ldmatrix. A pre-gathered+converted to fp16 in 2 chunks; GEMM split into two
// halves on two streams so cvt chunk 1 overlaps GEMM half 0.
// out[i] = weight[gate[i]] @ inp[i]
// ---------------------------------------------------------------------------

#define N_TOKENS 65536
#define D_IN     512
#define D_OUT    512
#define N_EXP    64

#define TM 128
#define TN 128
#define BK 64
#define NITER (D_IN / BK)       // 8
#define NSTAGE 3
#define MAX_TILES 1024
#define STRIDE_H 72             // halves per smem row (144B, conflict-free)
#define HALF_POS 32768          // position split between GEMM halves

#define ROWSTEP_B   (32 * STRIDE_H * 2)
#define TILE_B      (TM * STRIDE_H * 2)      // 18432
#define STAGE_B     (2 * TILE_B)
#define SM_A    1024
#define SMEM_TOTAL (SM_A + NSTAGE * STAGE_B) // 111616 -> 2 CTAs/SM

__device__ int g_counts[N_EXP];
__device__ int g_cursor[N_EXP];
__device__ int g_offsets[N_EXP];
__device__ int g_perm[N_TOKENS];
__device__ int g_tile_expert[MAX_TILES];
__device__ int g_tile_start[MAX_TILES];
__device__ int g_tile_rows[MAX_TILES];
__device__ int g_ntiles;

__device__ __align__(16) __half a_h[(N_TOKENS + TM) * D_IN];
__device__ __align__(16) __half w_h[N_EXP * D_OUT * D_IN];

// ---------------- prep kernels ----------------
__global__ void k_zero() {
    int t = threadIdx.x;
    if (t < N_EXP) { g_counts[t] = 0; g_cursor[t] = 0; }
}

__global__ void k_hist(const int4* __restrict__ gate4) {
    __shared__ int h[N_EXP];
    int t = threadIdx.x;
    if (t < N_EXP) h[t] = 0;
    __syncthreads();
    int4 g = gate4[blockIdx.x * blockDim.x + t];
    atomicAdd(&h[g.x], 1); atomicAdd(&h[g.y], 1);
    atomicAdd(&h[g.z], 1); atomicAdd(&h[g.w], 1);
    __syncthreads();
    if (t < N_EXP && h[t]) atomicAdd(&g_counts[t], h[t]);
}

__global__ void k_build() {
    __shared__ int ws[2], wt[2];
    int e = threadIdx.x;
    int c = g_counts[e];
    int x = c;
    #pragma unroll
    for (int d = 1; d < 32; d <<= 1) {
        int v = __shfl_up_sync(0xFFFFFFFFu, x, d);
        if ((e & 31) >= d) x += v;
    }
    if ((e & 31) == 31) ws[e >> 5] = x;
    __syncthreads();
    int off = x - c + ((e >= 32) ? ws[0] : 0);
    g_offsets[e] = off;

    int nt = (c + TM - 1) / TM;
    int y = nt;
    #pragma unroll
    for (int d = 1; d < 32; d <<= 1) {
        int v = __shfl_up_sync(0xFFFFFFFFu, y, d);
        if ((e & 31) >= d) y += v;
    }
    if ((e & 31) == 31) wt[e >> 5] = y;
    __syncthreads();
    int tbase = y - nt + ((e >= 32) ? wt[0] : 0);
    for (int s = 0, i = 0; s < c; s += TM, i++) {
        g_tile_expert[tbase + i] = e;
        g_tile_start[tbase + i]  = off + s;
        g_tile_rows[tbase + i]   = min(TM, c - s);
    }
    if (e == 63) g_ntiles = tbase + nt;
}

__global__ void k_scatter(const int* __restrict__ gate) {
    __shared__ int lh[N_EXP], lb[N_EXP];
    int t = threadIdx.x;
    if (t < N_EXP) lh[t] = 0;
    __syncthreads();
    int base = blockIdx.x * 1024;
    int4 g = ((const int4*)(gate + base))[t];
    int r0 = atomicAdd(&lh[g.x], 1);
    int r1 = atomicAdd(&lh[g.y], 1);
    int r2 = atomicAdd(&lh[g.z], 1);
    int r3 = atomicAdd(&lh[g.w], 1);
    __syncthreads();
    if (t < N_EXP) {
        int c = lh[t];
        lb[t] = c ? (g_offsets[t] + atomicAdd(&g_cursor[t], c)) : 0;
    }
    __syncthreads();
    int tok = base + t * 4;
    g_perm[lb[g.x] + r0] = tok + 0;
    g_perm[lb[g.y] + r1] = tok + 1;
    g_perm[lb[g.z] + r2] = tok + 2;
    g_perm[lb[g.w] + r3] = tok + 3;
}

// Gather+convert one chunk of permuted positions into a_h.
__global__ void k_cvt_inp(const float* __restrict__ inp, int base_pos, int npos) {
    int idx = blockIdx.x * blockDim.x + threadIdx.x;
    if ((idx >> 7) >= npos) return;
    int pos = base_pos + (idx >> 7), w = idx & 127;
    __half2* dst = (__half2*)(a_h + (size_t)pos * D_IN + w * 4);
    if (pos < N_TOKENS) {
        int row = g_perm[pos];
        float4 v = *(const float4*)(inp + (size_t)row * D_IN + w * 4);
        dst[0] = __floats2half2_rn(v.x, v.y);
        dst[1] = __floats2half2_rn(v.z, v.w);
    } else {
        dst[0] = __floats2half2_rn(0.f, 0.f);
        dst[1] = __floats2half2_rn(0.f, 0.f);
    }
}

__global__ void k_cvt_w(const float4* __restrict__ w4) {
    int idx = blockIdx.x * blockDim.x + threadIdx.x;
    float4 v = w4[idx];
    __half2* dst = (__half2*)(w_h + (size_t)idx * 4);
    dst[0] = __floats2half2_rn(v.x, v.y);
    dst[1] = __floats2half2_rn(v.z, v.w);
}

// ---------------- GEMM helpers ----------------
__device__ __forceinline__ uint32_t smem_u32(const void* p) {
    uint32_t a;
    asm("{ .reg .u64 t; cvta.to.shared.u64 t, %1; cvt.u32.u64 %0, t; }" : "=r"(a) : "l"(p));
    return a;
}
__device__ __forceinline__ void cp16(uint32_t dst, const void* src) {
    asm volatile("cp.async.cg.shared.global [%0], [%1], 16;"
                 :: "r"(dst), "l"(src) : "memory");
}
__device__ __forceinline__ void ldm_x4(uint32_t* r, uint32_t a) {
    asm volatile("ldmatrix.sync.aligned.m8n8.x4.shared.b16 {%0,%1,%2,%3}, [%4];"
                 : "=r"(r[0]), "=r"(r[1]), "=r"(r[2]), "=r"(r[3]) : "r"(a));
}
__device__ __forceinline__ void mma_f16(float* d, const uint32_t* a, const uint32_t* b) {
    asm volatile(
        "mma.sync.aligned.m16n8k16.row.col.f32.f16.f16.f32 "
        "{%0,%1,%2,%3}, {%4,%5,%6,%7}, {%8,%9}, {%0,%1,%2,%3};"
        : "+f"(d[0]), "+f"(d[1]), "+f"(d[2]), "+f"(d[3])
        : "r"(a[0]), "r"(a[1]), "r"(a[2]), "r"(a[3]), "r"(b[0]), "r"(b[1]));
}

// ---------------- tensor-core GEMM (per half) ----------------
__global__ __launch_bounds__(256, 2) void k_gemm(float* __restrict__ out, int half) {
    int tile = blockIdx.x;
    if (tile >= g_ntiles) return;
    int start = g_tile_start[tile];
    int belongs = (start + TM <= HALF_POS) ? 0 : 1;   // straddler -> half 1
    if (belongs != half) return;
    int e     = g_tile_expert[tile];
    int nrows = g_tile_rows[tile];
    int otile = blockIdx.y * TN;

    extern __shared__ char smem[];
    uint32_t sb = smem_u32(smem);
    int* rows_s = (int*)smem;

    int tid = threadIdx.x;
    int wid = tid >> 5, lid = tid & 31;
    int wm = wid & 1, wn = wid >> 1;
    int g  = lid >> 2, c = lid & 3;

    if (tid < TM) rows_s[tid] = (tid < nrows) ? g_perm[start + tid] : -1;
    __syncthreads();

    uint32_t a_lm = (uint32_t)((wm * 64 + (lid & 15)) * (STRIDE_H * 2) + (lid >> 4) * 16);
    uint32_t b_lm = (uint32_t)((wn * 32 + ((lid >> 4) & 1) * 8 + (lid & 7)) * (STRIDE_H * 2)
                               + ((lid >> 3) & 1) * 16);

    int row0 = tid >> 3, seg = tid & 7;
    const __half* asrc = a_h + (size_t)(start + row0) * D_IN + seg * 8;
    const __half* bsrc = w_h + (size_t)(e * D_OUT + otile + row0) * D_IN + seg * 8;
    uint32_t adst0 = sb + SM_A + row0 * (STRIDE_H * 2) + seg * 16;
    uint32_t bdst0 = adst0 + TILE_B;

    float acc[4][4][4];
    #pragma unroll
    for (int mi = 0; mi < 4; mi++)
        #pragma unroll
        for (int ni = 0; ni < 4; ni++)
            #pragma unroll
            for (int q = 0; q < 4; q++) acc[mi][ni][q] = 0.f;

    #pragma unroll
    for (int st = 0; st < 2; st++) {
        uint32_t so = st * STAGE_B;
        int kk = st * BK;
        #pragma unroll
        for (int l = 0; l < 4; l++) {
            cp16(adst0 + so + l * ROWSTEP_B, asrc + kk + (size_t)l * 32 * D_IN);
            cp16(bdst0 + so + l * ROWSTEP_B, bsrc + kk + (size_t)l * 32 * D_IN);
        }
        asm volatile("cp.async.commit_group;" ::: "memory");
    }

    for (int it = 0; it < NITER; it++) {
        if (it == NITER - 1)
            asm volatile("cp.async.wait_group 0;" ::: "memory");
        else
            asm volatile("cp.async.wait_group 1;" ::: "memory");
        __syncthreads();

        if (it + 2 < NITER) {
            uint32_t so = ((it + 2) % NSTAGE) * STAGE_B;
            int kk = (it + 2) * BK;
            #pragma unroll
            for (int l = 0; l < 4; l++) {
                cp16(adst0 + so + l * ROWSTEP_B, asrc + kk + (size_t)l * 32 * D_IN);
                cp16(bdst0 + so + l * ROWSTEP_B, bsrc + kk + (size_t)l * 32 * D_IN);
            }
            asm volatile("cp.async.commit_group;" ::: "memory");
        }

        uint32_t so = (it % NSTAGE) * STAGE_B;
        uint32_t aL = sb + SM_A + so + a_lm;
        uint32_t bL = sb + SM_A + so + TILE_B + b_lm;
        #pragma unroll
        for (int ks = 0; ks < 4; ks++) {
            uint32_t af[4][4], bf[2][4];
            #pragma unroll
            for (int mi = 0; mi < 4; mi++)
                ldm_x4(af[mi], aL + mi * (16 * STRIDE_H * 2) + ks * 32);
            #pragma unroll
            for (int p = 0; p < 2; p++)
                ldm_x4(bf[p], bL + p * (16 * STRIDE_H * 2) + ks * 32);
            #pragma unroll
            for (int mi = 0; mi < 4; mi++)
                #pragma unroll
                for (int ni = 0; ni < 4; ni++)
                    mma_f16(acc[mi][ni], af[mi], &bf[ni >> 1][(ni & 1) * 2]);
        }
    }

    #pragma unroll
    for (int mi = 0; mi < 4; mi++) {
        int r0 = wm * 64 + mi * 16 + g;
        int row0e = rows_s[r0];
        int row1e = rows_s[r0 + 8];
        #pragma unroll
        for (int ni = 0; ni < 4; ni++) {
            int col = otile + wn * 32 + ni * 8 + 2 * c;
            if (row0e >= 0)
                *(float2*)(out + (size_t)row0e * D_OUT + col) =
                    make_float2(acc[mi][ni][0], acc[mi][ni][1]);
            if (row1e >= 0)
                *(float2*)(out + (size_t)row1e * D_OUT + col) =
                    make_float2(acc[mi][ni][2], acc[mi][ni][3]);
        }
    }
}

extern "C" void kernel_launch(void* const* d_in, const int* in_sizes, int n_in,
                              void* d_out, int out_size) {
    const float* inp    = (const float*)d_in[0];
    const int*   gate   = (const int*)d_in[1];
    const float* weight = (const float*)d_in[2];
    float*       out    = (float*)d_out;

    static cudaStream_t s2 = nullptr;
    static cudaEvent_t ev_fork = nullptr, ev_w = nullptr, ev_c0 = nullptr, ev_g0 = nullptr;
    if (!s2) {
        cudaStreamCreateWithFlags(&s2, cudaStreamNonBlocking);
        cudaEventCreateWithFlags(&ev_fork, cudaEventDisableTiming);
        cudaEventCreateWithFlags(&ev_w, cudaEventDisableTiming);
        cudaEventCreateWithFlags(&ev_c0, cudaEventDisableTiming);
        cudaEventCreateWithFlags(&ev_g0, cudaEventDisableTiming);
    }

    cudaFuncSetAttribute(k_gemm, cudaFuncAttributeMaxDynamicSharedMemorySize, SMEM_TOTAL);

    // Fork: weight conversion on s2 (done well before GEMM half 0 launches).
    cudaEventRecord(ev_fork, 0);
    cudaStreamWaitEvent(s2, ev_fork, 0);
    k_cvt_w<<<(N_EXP * D_OUT * D_IN / 4) / 256, 256, 0, s2>>>((const float4*)weight);
    cudaEventRecord(ev_w, s2);

    // Token prep on stream 0.
    k_zero<<<1, 64>>>();
    k_hist<<<N_TOKENS / (256 * 4), 256>>>((const int4*)gate);
    k_build<<<1, 64>>>();
    k_scatter<<<N_TOKENS / 1024, 256>>>(gate);

    dim3 grid(640, D_OUT / TN);

    // cvt chunk 0, then GEMM half 0 on s2 (w_h already ready on s2).
    k_cvt_inp<<<(HALF_POS * 128) / 256, 256>>>(inp, 0, HALF_POS);
    cudaEventRecord(ev_c0, 0);
    cudaStreamWaitEvent(s2, ev_c0, 0);
    k_gemm<<<grid, 256, SMEM_TOTAL, s2>>>(out, 0);
    cudaEventRecord(ev_g0, s2);

    // cvt chunk 1 overlaps GEMM half 0; GEMM half 1 on stream 0 after it.
    k_cvt_inp<<<((HALF_POS + TM) * 128 + 255) / 256, 256>>>(inp, HALF_POS, HALF_POS + TM);
    cudaStreamWaitEvent(0, ev_w, 0);
    k_gemm<<<grid, 256, SMEM_TOTAL, 0>>>(out, 1);

    // Join s2 back into the capture-origin stream.
    cudaStreamWaitEvent(0, ev_g0, 0);
}